// round 11
// baseline (speedup 1.0000x reference)
#include <cuda_runtime.h>
#include <cstdint>

#define N     8192
#define K1    31
#define CAP   256      // per-line candidate capacity (mean 88, max ~135)
#define PIVOT 2.3f     // P(z>2.3)=0.0107
#define NF4   ((size_t)N * N / 4)
#define NREC  ((size_t)N * N / 128)   // one record per warp-of-128-elements
#define FULLM 0xFFFFFFFFu

__device__ uint4              g_bits[NREC];               // 8 MB candidate bitmask
__device__ float              g_slots[NREC * 4];          // 32 MB value slots (first 4/record)
__device__ unsigned long long g_colcand[(size_t)N * CAP]; // 16 MB
__device__ unsigned long long g_rowcand[(size_t)N * CAP]; // 16 MB
__device__ int                g_colcnt[N];
__device__ int                g_rowcnt[N];
__device__ unsigned long long g_rowth[N];
__device__ unsigned long long g_colth[N];

// Monotone map float -> uint32 (larger float => larger key)
__device__ __forceinline__ unsigned int fkey(float x) {
    unsigned int u = __float_as_uint(x);
    return (u & 0x80000000u) ? ~u : (u | 0x80000000u);
}
__device__ __forceinline__ float inv_fkey(unsigned int k) {
    unsigned int u = (k & 0x80000000u) ? (k ^ 0x80000000u) : ~k;
    return __uint_as_float(u);
}
// Composite key: value-major, lower index wins ties (stable top_k semantics)
__device__ __forceinline__ unsigned long long ckey(float x, int idx) {
    return ((unsigned long long)fkey(x) << 32) | (unsigned int)(N - 1 - idx);
}

// block-level exact fallback: K1-th largest key of a full line (exactness
// guard for arbitrary inputs; statistically never triggered)
template <bool ROW>
__device__ unsigned long long block_fallback(const float* __restrict__ A, int line) {
    __shared__ unsigned long long red[128];
    unsigned long long prev = 0xFFFFFFFFFFFFFFFFull;
    for (int it = 0; it < K1; it++) {
        unsigned long long best = 0;
        for (int t = threadIdx.x; t < N; t += 128) {
            float x = ROW ? A[(size_t)line * N + t] : A[(size_t)t * N + line];
            unsigned long long k = ckey(x, t);
            if (k < prev && k > best) best = k;
        }
        red[threadIdx.x] = best;
        __syncthreads();
        for (int s = 64; s > 0; s >>= 1) {
            if (threadIdx.x < s) {
                unsigned long long o = red[threadIdx.x + s];
                if (o > red[threadIdx.x]) red[threadIdx.x] = o;
            }
            __syncthreads();
        }
        prev = red[0];
        __syncthreads();
    }
    return prev;
}

// K1: streaming pass. Reads A, zeros out, emits bitmask + first-4 candidate
// VALUES per 128-element warp record. No atomics, no barriers.
// Record gw: element (gw*128 + lane*4 + c); candidate ordinal within record
// is word-major (c asc) then lane asc.
__global__ __launch_bounds__(256) void stream_kernel(const float* __restrict__ A,
                                                     float* __restrict__ out) {
    if (blockIdx.x < N / 256) g_colcnt[blockIdx.x * 256 + threadIdx.x] = 0;
    const size_t g = (size_t)blockIdx.x * 256 + threadIdx.x;  // float4 index
    float4 v = ((const float4*)A)[g];
    const float4 zz = {0.0f, 0.0f, 0.0f, 0.0f};
    ((float4*)out)[g] = zz;
    unsigned m0 = __ballot_sync(FULLM, v.x > PIVOT);
    unsigned m1 = __ballot_sync(FULLM, v.y > PIVOT);
    unsigned m2 = __ballot_sync(FULLM, v.z > PIVOT);
    unsigned m3 = __ballot_sync(FULLM, v.w > PIVOT);
    const int lane = threadIdx.x & 31;
    const unsigned lt = (1u << lane) - 1u;
    const size_t gw = g >> 5;
    const int pw1 = __popc(m0), pw2 = pw1 + __popc(m1), pw3 = pw2 + __popc(m2);
    if (v.x > PIVOT) { int o = __popc(m0 & lt);       if (o < 4) g_slots[gw * 4 + o] = v.x; }
    if (v.y > PIVOT) { int o = pw1 + __popc(m1 & lt); if (o < 4) g_slots[gw * 4 + o] = v.y; }
    if (v.z > PIVOT) { int o = pw2 + __popc(m2 & lt); if (o < 4) g_slots[gw * 4 + o] = v.z; }
    if (v.w > PIVOT) { int o = pw3 + __popc(m3 & lt); if (o < 4) g_slots[gw * 4 + o] = v.w; }
    if (lane == 0) {
        uint4 w = {m0, m1, m2, m3};
        g_bits[gw] = w;
    }
}

// K2: block per row (128 thr). Threads 0..63 each own one record of the row:
// coalesced bits+slots load (no dependent gather), decode, push column
// candidates, store row keys; rank-count -> g_rowth; store row list for K4.
__global__ __launch_bounds__(128) void rowth_kernel(const float* __restrict__ A) {
    const int row = blockIdx.x, t = threadIdx.x, lane = t & 31, w = t >> 5;
    __shared__ unsigned long long keys[CAP];
    __shared__ int wsum[2];
    uint4 b = {0, 0, 0, 0};
    float4 sv = {0, 0, 0, 0};
    int cnt = 0;
    if (t < 64) {
        b = g_bits[(size_t)row * 64 + t];
        sv = ((const float4*)g_slots)[(size_t)row * 64 + t];
        cnt = __popc(b.x) + __popc(b.y) + __popc(b.z) + __popc(b.w);
    }
    int incl = cnt;
#pragma unroll
    for (int d = 1; d < 32; d <<= 1) {
        int vv = __shfl_up_sync(FULLM, incl, d);
        if (lane >= d) incl += vv;
    }
    if (w < 2 && lane == 31) wsum[w] = incl;
    __syncthreads();
    const int total = wsum[0] + wsum[1];
    const bool ok = (total >= K1 && total <= CAP);
    int base = incl - cnt + ((w == 1) ? wsum[0] : 0);

    if (t < 64) {
        unsigned words[4] = {b.x, b.y, b.z, b.w};
        float slotv[4] = {sv.x, sv.y, sv.z, sv.w};
        int o = 0;
#pragma unroll
        for (int c = 0; c < 4; c++) {
            unsigned wb = words[c];
            while (wb) {
                int l = __ffs(wb) - 1;
                wb &= wb - 1;
                int j = t * 128 + l * 4 + c;
                float x = (o < 4) ? slotv[o] : A[(size_t)row * N + j];  // overflow: rare
                unsigned long long k = ckey(x, j);
                if (ok) keys[base + o] = k;
                o++;
                int cs = atomicAdd(&g_colcnt[j], 1);
                if (cs < CAP) g_colcand[(size_t)j * CAP + cs] = ckey(x, row);
            }
        }
    }
    __syncthreads();

    if (ok) {
        for (int s = t; s < total; s += 128) {
            unsigned long long kt = keys[s];
            int r = 0;
            for (int m = 0; m < total; m++) r += (keys[m] > kt);
            if (r == K1 - 1) g_rowth[row] = kt;        // exactly one writer
            g_rowcand[(size_t)row * CAP + s] = kt;     // list for K4
        }
        if (t == 0) g_rowcnt[row] = total;
    } else {
        unsigned long long th = block_fallback<true>(A, row);
        if (t == 0) { g_rowth[row] = th; g_rowcnt[row] = -1; }
    }
}

// K3: block per column (128 thr). colth by rank-counting the candidate list.
__global__ __launch_bounds__(128) void colth_kernel(const float* __restrict__ A) {
    const int j = blockIdx.x, t = threadIdx.x;
    const int c = g_colcnt[j];
    __shared__ unsigned long long cand[CAP];
    if (c >= K1 && c <= CAP) {
        for (int s = t; s < c; s += 128)
            cand[s] = g_colcand[(size_t)j * CAP + s];
        __syncthreads();
        for (int s = t; s < c; s += 128) {
            unsigned long long kt = cand[s];
            int r = 0;
            for (int m = 0; m < c; m++) r += (cand[m] > kt);
            if (r == K1 - 1) g_colth[j] = kt;
        }
    } else {
        unsigned long long th = block_fallback<false>(A, j);
        if (t == 0) g_colth[j] = th;
    }
}

// K4: scatter survivors from ROW lists (row-major writes). Unhealthy rows
// (g_rowcnt=-1) do a full-row rescan: any survivor there may have value
// <= PIVOT, and the rescan covers it exactly.
__global__ __launch_bounds__(128) void scatter_kernel(const float* __restrict__ A,
                                                      float* __restrict__ out) {
    const int row = blockIdx.x, t = threadIdx.x;
    const int cnt = g_rowcnt[row];
    const unsigned long long rth = g_rowth[row];
    if (cnt >= 0) {
        for (int s = t; s < cnt; s += 128) {
            unsigned long long k = g_rowcand[(size_t)row * CAP + s];
            if (k < rth) continue;
            int j = N - 1 - (int)(unsigned int)(k & 0xFFFFFFFFu);
            if (j == row) continue;
            float x = inv_fkey((unsigned int)(k >> 32));
            if (ckey(x, row) >= g_colth[j])
                out[(size_t)row * N + j] = x;
        }
    } else {
        for (int j = t; j < N; j += 128) {
            if (j == row) continue;
            float x = A[(size_t)row * N + j];
            if (ckey(x, j) >= rth && ckey(x, row) >= g_colth[j])
                out[(size_t)row * N + j] = x;
        }
    }
}

extern "C" void kernel_launch(void* const* d_in, const int* in_sizes, int n_in,
                              void* d_out, int out_size) {
    const float* A = (const float*)d_in[0];
    float* out = (float*)d_out;
    stream_kernel<<<(unsigned)(NF4 / 256), 256>>>(A, out);
    rowth_kernel<<<N, 128>>>(A);
    colth_kernel<<<N, 128>>>(A);
    scatter_kernel<<<N, 128>>>(A, out);
}